// round 13
// baseline (speedup 1.0000x reference)
#include <cuda_runtime.h>
#include <cuda_fp16.h>
#include <cstdint>
#include <math.h>

#define BB 4
#define SS 2048
#define DD 1024

#define LDBY 144                        // smem row stride bytes (128B data + 16B pad)
#define TILE_A_BY (128 * LDBY)          // 18432 B : 128x64 fp16 tile (A)
#define TILE_B_BY (256 * LDBY)          // 36864 B : 256x64 fp16 tile (B)
#define NSTAGE 3
#define STAGE_B (TILE_A_BY + TILE_B_BY) // 55296
#define SMEM_BYTES (NSTAGE * STAGE_B)   // 165888, 1 CTA/SM

// ---------------------------------------------------------------------------
// Scratch (__device__ globals; allocation-free rule)
// ---------------------------------------------------------------------------
__device__ __align__(16) __half g_x[BB*SS*DD];
__device__ __align__(16) __half g_w[3][DD*DD];
__device__ __align__(16) __half g_q[BB*SS*DD];
__device__ __align__(16) __half g_k[BB*SS*DD];
__device__ __align__(16) __half g_vT[BB*DD*SS];     // V^T [b][d][s]
__device__ __align__(16) __half g_ph[BB*SS*SS];     // p~ = exp(s/32), causal-masked
__device__ __align__(16) float  g_sum[BB*SS];       // row sums (atomic-accumulated)

// ---------------------------------------------------------------------------
// PTX primitives
// ---------------------------------------------------------------------------
__device__ __forceinline__ void mma_f16(float* d, const uint32_t* a, const uint32_t* b) {
    asm volatile(
        "mma.sync.aligned.m16n8k16.row.col.f32.f16.f16.f32 "
        "{%0,%1,%2,%3}, {%4,%5,%6,%7}, {%8,%9}, {%0,%1,%2,%3};"
        : "+f"(d[0]), "+f"(d[1]), "+f"(d[2]), "+f"(d[3])
        : "r"(a[0]), "r"(a[1]), "r"(a[2]), "r"(a[3]), "r"(b[0]), "r"(b[1]));
}
#define LDSM4(r0, r1, r2, r3, addr) \
    asm volatile("ldmatrix.sync.aligned.m8n8.x4.shared.b16 {%0,%1,%2,%3}, [%4];" \
                 : "=r"(r0), "=r"(r1), "=r"(r2), "=r"(r3) : "r"(addr))
#define CP_ASYNC16(dst, src) \
    asm volatile("cp.async.cg.shared.global [%0], [%1], 16;" :: "r"(dst), "l"(src))
#define CP_COMMIT() asm volatile("cp.async.commit_group;" ::: "memory")
#define CP_WAIT1()  asm volatile("cp.async.wait_group 1;" ::: "memory")

// ---------------------------------------------------------------------------
// cp.async: ROWS x 64 fp16 tile (K-major, row stride ld elems). 256 threads.
// ---------------------------------------------------------------------------
template <int ROWS>
__device__ __forceinline__ void g2s_tile(uint32_t dst, const __half* __restrict__ g,
                                         size_t ld, int k0, int tid) {
#pragma unroll
    for (int i = 0; i < ROWS / 32; i++) {
        int slot = tid + (i << 8);
        int row = slot >> 3;
        int c = slot & 7;               // 16B chunk
        CP_ASYNC16(dst + row * LDBY + c * 16, g + (size_t)row * ld + k0 + c * 8);
    }
}

// ---------------------------------------------------------------------------
// Mainloop: acc[4][8][4] += A[128,K] . B[256,K]^T  (fp16, K-chunk 64)
// 256 threads, 8 warps in 2x4 grid, warp tile 64x64, 3-stage cp.async pipeline,
// ONE __syncthreads per chunk (compute-then-prefetch ordering). 1 CTA/SM.
// ---------------------------------------------------------------------------
__device__ __forceinline__ void mma_mainloop(
    const __half* __restrict__ A, const __half* __restrict__ B,
    size_t lda, size_t ldb, int nch, uint32_t smem, float acc[4][8][4]) {

    const int tid = threadIdx.x;
    const int lane = tid & 31, wid = tid >> 5;
    const int wm = wid >> 2, wn = wid & 3;      // 2 x 4 warp grid

    const uint32_t a_off = (uint32_t)(wm * 64 + (lane & 15)) * LDBY + ((lane & 16) ? 16u : 0u);
    const uint32_t b_off = (uint32_t)(wn * 64 + (lane & 7) + ((lane & 16) ? 8 : 0)) * LDBY
                         + ((lane & 8) ? 16u : 0u);

    // prologue: chunks 0, 1
#pragma unroll
    for (int s = 0; s < 2; s++) {
        if (s < nch) {
            uint32_t st = smem + s * STAGE_B;
            g2s_tile<128>(st,             A, lda, s * 64, tid);
            g2s_tile<256>(st + TILE_A_BY, B, ldb, s * 64, tid);
        }
        CP_COMMIT();
    }

    int sidx = 0;
    for (int c = 0; c < nch; c++) {
        CP_WAIT1();
        __syncthreads();

        const uint32_t st = smem + sidx * STAGE_B;
#pragma unroll
        for (int ks = 0; ks < 4; ks++) {
            const uint32_t ka = st + a_off + ks * 32;
            const uint32_t kb = st + TILE_A_BY + b_off + ks * 32;
            uint32_t ah[4][4], bb[8][2];
#pragma unroll
            for (int fm = 0; fm < 4; fm++)
                LDSM4(ah[fm][0], ah[fm][1], ah[fm][2], ah[fm][3], ka + fm * 16 * LDBY);
#pragma unroll
            for (int p = 0; p < 4; p++)
                LDSM4(bb[2*p][0], bb[2*p][1], bb[2*p+1][0], bb[2*p+1][1], kb + p * 16 * LDBY);
#pragma unroll
            for (int fm = 0; fm < 4; fm++)
#pragma unroll
                for (int fn = 0; fn < 8; fn++) mma_f16(acc[fm][fn], ah[fm], bb[fn]);
        }

        // prefetch chunk c+2 into stage (sidx+2)%3
        if (c + 2 < nch) {
            int s2 = sidx + 2; if (s2 >= NSTAGE) s2 -= NSTAGE;
            uint32_t stw = smem + s2 * STAGE_B;
            const int k0 = (c + 2) * 64;
            g2s_tile<128>(stw,             A, lda, k0, tid);
            g2s_tile<256>(stw + TILE_A_BY, B, ldb, k0, tid);
        }
        CP_COMMIT();
        if (++sidx == NSTAGE) sidx = 0;
    }
}

#define ZERO_ACC(acc) \
    do { _Pragma("unroll") for (int i = 0; i < 4; i++) \
         _Pragma("unroll") for (int j = 0; j < 8; j++) \
         _Pragma("unroll") for (int r = 0; r < 4; r++) (acc)[i][j][r] = 0.0f; } while (0)

// ---------------------------------------------------------------------------
// Kernel 0: convert x, Wq, Wk, Wv to fp16; zero g_sum
// ---------------------------------------------------------------------------
__global__ __launch_bounds__(256) void convert_all(
    const float* __restrict__ x, const float* __restrict__ wq,
    const float* __restrict__ wk, const float* __restrict__ wv) {
    const int which = blockIdx.y;
    const float* src = (which == 0) ? x : (which == 1) ? wq : (which == 2) ? wk : wv;
    __half* dst = (which == 0) ? g_x : g_w[which - 1];
    const int n = (which == 0) ? BB * SS * DD : DD * DD;
    for (int i = blockIdx.x * 256 + threadIdx.x; i * 2 < n; i += gridDim.x * 256) {
        float2 f = *(const float2*)(src + i * 2);
        __half2 h; h.x = __float2half(f.x); h.y = __float2half(f.y);
        *(__half2*)(dst + i * 2) = h;
    }
    if (which == 0) {
        for (int i = blockIdx.x * 256 + threadIdx.x; i < BB * SS; i += gridDim.x * 256)
            g_sum[i] = 0.0f;
    }
}

// ---------------------------------------------------------------------------
// Kernel 1: QKV.  CTA 128(M) x 256(N).  z=0->Q, z=1->K, z=2->V^T (transpose)
// ---------------------------------------------------------------------------
__global__ __launch_bounds__(256, 1) void qkv_mma() {
    extern __shared__ char smraw[];
    const uint32_t smem = (uint32_t)__cvta_generic_to_shared(smraw);
    const int z = blockIdx.z;
    const int m0 = blockIdx.y * 128;
    const int n0 = blockIdx.x * 256;

    float acc[4][8][4];
    ZERO_ACC(acc);

    mma_mainloop(g_x + (size_t)m0 * DD, g_w[z] + (size_t)n0 * DD,
                 DD, DD, DD / 64, smem, acc);

    const int lane = threadIdx.x & 31, wid = threadIdx.x >> 5;
    const int wm = wid >> 2, wn = wid & 3;
    const int g = lane >> 2, tg = lane & 3;

    if (z < 2) {
        __half* D = z ? g_k : g_q;
#pragma unroll
        for (int fm = 0; fm < 4; fm++)
#pragma unroll
            for (int fn = 0; fn < 8; fn++) {
                const int n = n0 + wn * 64 + fn * 8 + tg * 2;
#pragma unroll
                for (int half = 0; half < 2; half++) {
                    const int m = m0 + wm * 64 + fm * 16 + g + half * 8;
                    __half2 h2;
                    h2.x = __float2half(acc[fm][fn][half * 2]);
                    h2.y = __float2half(acc[fm][fn][half * 2 + 1]);
                    *(__half2*)(D + (size_t)m * DD + n) = h2;
                }
            }
    } else {
        // transpose 128x256 tile through smem, then coalesced store to V^T
        __syncthreads();                      // mainloop smem reads done
        __half* smt = (__half*)smraw;         // [n_local][m_local], stride 136
#pragma unroll
        for (int fm = 0; fm < 4; fm++)
#pragma unroll
            for (int fn = 0; fn < 8; fn++) {
                const int nl = wn * 64 + fn * 8 + tg * 2;
#pragma unroll
                for (int half = 0; half < 2; half++) {
                    const int ml = wm * 64 + fm * 16 + g + half * 8;
                    smt[(nl)     * 136 + ml] = __float2half(acc[fm][fn][half * 2]);
                    smt[(nl + 1) * 136 + ml] = __float2half(acc[fm][fn][half * 2 + 1]);
                }
            }
        __syncthreads();
        const int b = m0 >> 11, ml0 = m0 & (SS - 1);
        const size_t rowbase = (size_t)b * DD * SS + (size_t)(n0 + threadIdx.x) * SS + ml0;
#pragma unroll
        for (int c16 = 0; c16 < 16; c16++) {
            uint4 v = *(uint4*)(smt + threadIdx.x * 136 + c16 * 8);
            *(uint4*)(g_vT + rowbase + c16 * 8) = v;
        }
    }
}

// ---------------------------------------------------------------------------
// Kernel 2: causal scores -> p~ = exp(s/32) fp16 (masked) + fused row sums
// CTA 128(M) x 256(N); tiles with jt <= it>>1: 72 per batch.
// ---------------------------------------------------------------------------
__global__ __launch_bounds__(256, 1) void scores_mma() {
    extern __shared__ char smraw[];
    const uint32_t smem = (uint32_t)__cvta_generic_to_shared(smraw);
    const int t = blockIdx.x;
    int it = 0, base = 0;
    while (base + (it >> 1) + 1 <= t) { base += (it >> 1) + 1; it++; }
    const int jt = t - base;
    const int b = blockIdx.y;
    const int m0 = it * 128, n0 = jt * 256;

    float acc[4][8][4];
    ZERO_ACC(acc);

    const size_t ao = ((size_t)b * SS + m0) * DD;
    const size_t bo = ((size_t)b * SS + n0) * DD;
    mma_mainloop(g_q + ao, g_k + bo, DD, DD, DD / 64, smem, acc);

    const int lane = threadIdx.x & 31, wid = threadIdx.x >> 5;
    const int wm = wid >> 2, wn = wid & 3;
    const int g = lane >> 2, tg = lane & 3;
    __half* C = g_ph + (size_t)b * SS * SS;
    const float alpha = 1.0f / 32.0f;
    const bool diag = (jt == (it >> 1));

#pragma unroll
    for (int fm = 0; fm < 4; fm++) {
#pragma unroll
        for (int half = 0; half < 2; half++) {
            const int m = m0 + wm * 64 + fm * 16 + g + half * 8;
            float rsum = 0.0f;
#pragma unroll
            for (int fn = 0; fn < 8; fn++) {
                const int n = n0 + wn * 64 + fn * 8 + tg * 2;
                float e0 = __expf(acc[fm][fn][half * 2] * alpha);
                float e1 = __expf(acc[fm][fn][half * 2 + 1] * alpha);
                if (diag) {
                    if (n > m) e0 = 0.0f;
                    if (n + 1 > m) e1 = 0.0f;
                }
                rsum += e0 + e1;
                __half2 h2; h2.x = __float2half(e0); h2.y = __float2half(e1);
                *(__half2*)(C + (size_t)m * SS + n) = h2;
            }
            // reduce across the 4 tg lanes (same row m)
            rsum += __shfl_xor_sync(0xffffffffu, rsum, 1);
            rsum += __shfl_xor_sync(0xffffffffu, rsum, 2);
            if (tg == 0) atomicAdd(&g_sum[b * SS + m], rsum);
        }
    }
}

// ---------------------------------------------------------------------------
// Kernel 3: O = (p~ @ V) / row_sum.  CTA 128(M) x 256(N).  Long tiles first.
// ---------------------------------------------------------------------------
__global__ __launch_bounds__(256, 1) void pv_mma(float* __restrict__ out) {
    extern __shared__ char smraw[];
    const uint32_t smem = (uint32_t)__cvta_generic_to_shared(smraw);
    const int b = blockIdx.z;
    const int it = (SS / 128 - 1) - blockIdx.y;   // 15..0, big tiles first
    const int m0 = it * 128;
    const int n0 = blockIdx.x * 256;
    const int nch = (it + 1) * 2;                 // kend = (it+1)*128, chunks of 64

    float acc[4][8][4];
    ZERO_ACC(acc);

    const size_t ao = ((size_t)b * SS + m0) * SS;
    const size_t bo = (size_t)b * DD * SS + (size_t)n0 * SS;
    mma_mainloop(g_ph + ao, g_vT + bo, SS, SS, nch, smem, acc);

    const int lane = threadIdx.x & 31, wid = threadIdx.x >> 5;
    const int wm = wid >> 2, wn = wid & 3;
    const int g = lane >> 2, tg = lane & 3;
    float* C = out + (size_t)b * SS * DD;

    float invm[4][2];
#pragma unroll
    for (int fm = 0; fm < 4; fm++)
#pragma unroll
        for (int half = 0; half < 2; half++)
            invm[fm][half] = 1.0f / g_sum[b * SS + m0 + wm * 64 + fm * 16 + g + half * 8];

#pragma unroll
    for (int fm = 0; fm < 4; fm++)
#pragma unroll
        for (int fn = 0; fn < 8; fn++) {
            const int n = n0 + wn * 64 + fn * 8 + tg * 2;
#pragma unroll
            for (int half = 0; half < 2; half++) {
                const int m = m0 + wm * 64 + fm * 16 + g + half * 8;
                float2 v;
                v.x = acc[fm][fn][half * 2]     * invm[fm][half];
                v.y = acc[fm][fn][half * 2 + 1] * invm[fm][half];
                *(float2*)(C + (size_t)m * DD + n) = v;
            }
        }
}

// ---------------------------------------------------------------------------
extern "C" void kernel_launch(void* const* d_in, const int* in_sizes, int n_in,
                              void* d_out, int out_size) {
    const float* x  = (const float*)d_in[0];
    const float* wq = (const float*)d_in[1];
    const float* wk = (const float*)d_in[2];
    const float* wv = (const float*)d_in[3];
    float* out = (float*)d_out;
    (void)in_sizes; (void)n_in; (void)out_size;

    static bool attr_done = false;
    if (!attr_done) {
        cudaFuncSetAttribute(qkv_mma,    cudaFuncAttributeMaxDynamicSharedMemorySize, SMEM_BYTES);
        cudaFuncSetAttribute(scores_mma, cudaFuncAttributeMaxDynamicSharedMemorySize, SMEM_BYTES);
        cudaFuncSetAttribute(pv_mma,     cudaFuncAttributeMaxDynamicSharedMemorySize, SMEM_BYTES);
        attr_done = true;
    }

    // 0) convert x, W to fp16; zero row sums
    convert_all<<<dim3(1024, 4), 256>>>(x, wq, wk, wv);

    // 1) Q, K, V^T projections
    qkv_mma<<<dim3(DD / 256, (BB * SS) / 128, 3), 256, SMEM_BYTES>>>();

    // 2) causal scores -> exp(s/32) fp16 (masked) + fused row sums
    scores_mma<<<dim3(72, BB), 256, SMEM_BYTES>>>();

    // 3) O = (p~ @ V) / sum
    pv_mma<<<dim3(DD / 256, SS / 128, BB), 256, SMEM_BYTES>>>(out);
}

// round 14
// speedup vs baseline: 1.0862x; 1.0862x over previous
#include <cuda_runtime.h>
#include <cuda_fp16.h>
#include <cstdint>
#include <math.h>

#define BB 4
#define SS 2048
#define DD 1024

#define LDBY 144                    // smem row stride bytes (128B data + 16B pad)
#define TILE_BY (128 * LDBY)        // 18432 B : 128x64 fp16 tile
#define NSTAGE 3
#define STAGE_B (2 * TILE_BY)       // A, B per stage = 36864
#define SMEM_BYTES (NSTAGE * STAGE_B)   // 110592 per CTA; 2 CTAs/SM = 221184

// ---------------------------------------------------------------------------
// Scratch (__device__ globals; allocation-free rule)
// ---------------------------------------------------------------------------
__device__ __align__(16) __half g_x[BB*SS*DD];
__device__ __align__(16) __half g_w[3][DD*DD];
__device__ __align__(16) __half g_q[BB*SS*DD];
__device__ __align__(16) __half g_k[BB*SS*DD];
__device__ __align__(16) __half g_vT[BB*DD*SS];     // V^T [b][d][s]
__device__ __align__(16) __half g_ph[BB*SS*SS];     // p~ = exp(s/32), causal-masked
__device__ __align__(16) float  g_sum[BB*SS];       // row sums (atomic-accumulated)

// ---------------------------------------------------------------------------
// PTX primitives
// ---------------------------------------------------------------------------
__device__ __forceinline__ void mma_f16(float* d, const uint32_t* a, const uint32_t* b) {
    asm volatile(
        "mma.sync.aligned.m16n8k16.row.col.f32.f16.f16.f32 "
        "{%0,%1,%2,%3}, {%4,%5,%6,%7}, {%8,%9}, {%0,%1,%2,%3};"
        : "+f"(d[0]), "+f"(d[1]), "+f"(d[2]), "+f"(d[3])
        : "r"(a[0]), "r"(a[1]), "r"(a[2]), "r"(a[3]), "r"(b[0]), "r"(b[1]));
}
#define LDSM4(r0, r1, r2, r3, addr) \
    asm volatile("ldmatrix.sync.aligned.m8n8.x4.shared.b16 {%0,%1,%2,%3}, [%4];" \
                 : "=r"(r0), "=r"(r1), "=r"(r2), "=r"(r3) : "r"(addr))
#define CP_ASYNC16(dst, src) \
    asm volatile("cp.async.cg.shared.global [%0], [%1], 16;" :: "r"(dst), "l"(src))
#define CP_COMMIT() asm volatile("cp.async.commit_group;" ::: "memory")
#define CP_WAIT1()  asm volatile("cp.async.wait_group 1;" ::: "memory")

// ---------------------------------------------------------------------------
// cp.async: one 128x64 fp16 tile (K-major, row stride ld elems). 128 threads.
// ---------------------------------------------------------------------------
__device__ __forceinline__ void g2s_tile(uint32_t dst, const __half* __restrict__ g,
                                         size_t ld, int k0, int tid) {
#pragma unroll
    for (int i = 0; i < 8; i++) {
        int slot = tid + (i << 7);      // 0..1023
        int row = slot >> 3;            // 0..127
        int c = slot & 7;               // 16B chunk
        CP_ASYNC16(dst + row * LDBY + c * 16, g + (size_t)row * ld + k0 + c * 8);
    }
}

// ---------------------------------------------------------------------------
// Fragment load for one ks (k-16 slice): 4 A-LDSM + 4 B-LDSM
// ---------------------------------------------------------------------------
__device__ __forceinline__ void ld_frags(uint32_t st, uint32_t a_off, uint32_t b_off,
                                         int ks, uint32_t ah[4][4], uint32_t bb[8][2]) {
    const uint32_t ka = st + a_off + ks * 32;
    const uint32_t kb = st + TILE_BY + b_off + ks * 32;
#pragma unroll
    for (int fm = 0; fm < 4; fm++)
        LDSM4(ah[fm][0], ah[fm][1], ah[fm][2], ah[fm][3], ka + fm * 16 * LDBY);
#pragma unroll
    for (int p = 0; p < 4; p++)
        LDSM4(bb[2*p][0], bb[2*p][1], bb[2*p+1][0], bb[2*p+1][1], kb + p * 16 * LDBY);
}

// ---------------------------------------------------------------------------
// Mainloop: acc[4][8][4] += A[128,K] . B[128,K]^T  (fp16, K-chunk 64)
// 128 threads, 4 warps 2x2, warp tile 64x64, 3-stage cp.async pipeline,
// double-buffered register fragments (LDSM of ks+1 before MMAs of ks).
// ---------------------------------------------------------------------------
__device__ __forceinline__ void mma_mainloop(
    const __half* __restrict__ A, const __half* __restrict__ B,
    size_t lda, size_t ldb, int nch, uint32_t smem, float acc[4][8][4]) {

    const int tid = threadIdx.x;
    const int lane = tid & 31, wid = tid >> 5;
    const int wm = wid >> 1, wn = wid & 1;

    const uint32_t a_off = (uint32_t)(wm * 64 + (lane & 15)) * LDBY + ((lane & 16) ? 16u : 0u);
    const uint32_t b_off = (uint32_t)(wn * 64 + (lane & 7) + ((lane & 16) ? 8 : 0)) * LDBY
                         + ((lane & 8) ? 16u : 0u);

    // prologue: chunks 0, 1
#pragma unroll
    for (int s = 0; s < 2; s++) {
        if (s < nch) {
            uint32_t st = smem + s * STAGE_B;
            g2s_tile(st,           A, lda, s * 64, tid);
            g2s_tile(st + TILE_BY, B, ldb, s * 64, tid);
        }
        CP_COMMIT();
    }

    uint32_t ah[2][4][4], bb[2][8][2];
    int sidx = 0;
    for (int c = 0; c < nch; c++) {
        CP_WAIT1();
        __syncthreads();

        const uint32_t st = smem + sidx * STAGE_B;
        ld_frags(st, a_off, b_off, 0, ah[0], bb[0]);
#pragma unroll
        for (int ks = 0; ks < 4; ks++) {
            const int cur = ks & 1, nxt = cur ^ 1;
            if (ks < 3) ld_frags(st, a_off, b_off, ks + 1, ah[nxt], bb[nxt]);
#pragma unroll
            for (int fm = 0; fm < 4; fm++)
#pragma unroll
                for (int fn = 0; fn < 8; fn++) mma_f16(acc[fm][fn], ah[cur][fm], bb[cur][fn]);
        }

        // prefetch chunk c+2 into stage (sidx+2)%3
        if (c + 2 < nch) {
            int s2 = sidx + 2; if (s2 >= NSTAGE) s2 -= NSTAGE;
            uint32_t stw = smem + s2 * STAGE_B;
            const int k0 = (c + 2) * 64;
            g2s_tile(stw,           A, lda, k0, tid);
            g2s_tile(stw + TILE_BY, B, ldb, k0, tid);
        }
        CP_COMMIT();
        if (++sidx == NSTAGE) sidx = 0;
    }
}

#define ZERO_ACC(acc) \
    do { _Pragma("unroll") for (int i = 0; i < 4; i++) \
         _Pragma("unroll") for (int j = 0; j < 8; j++) \
         _Pragma("unroll") for (int r = 0; r < 4; r++) (acc)[i][j][r] = 0.0f; } while (0)

// ---------------------------------------------------------------------------
// Kernel 0: convert x, Wq, Wk, Wv to fp16; zero g_sum
// ---------------------------------------------------------------------------
__global__ __launch_bounds__(256) void convert_all(
    const float* __restrict__ x, const float* __restrict__ wq,
    const float* __restrict__ wk, const float* __restrict__ wv) {
    const int which = blockIdx.y;
    const float* src = (which == 0) ? x : (which == 1) ? wq : (which == 2) ? wk : wv;
    __half* dst = (which == 0) ? g_x : g_w[which - 1];
    const int n = (which == 0) ? BB * SS * DD : DD * DD;
    for (int i = blockIdx.x * 256 + threadIdx.x; i * 2 < n; i += gridDim.x * 256) {
        float2 f = *(const float2*)(src + i * 2);
        __half2 h; h.x = __float2half(f.x); h.y = __float2half(f.y);
        *(__half2*)(dst + i * 2) = h;
    }
    if (which == 0) {
        for (int i = blockIdx.x * 256 + threadIdx.x; i < BB * SS; i += gridDim.x * 256)
            g_sum[i] = 0.0f;
    }
}

// ---------------------------------------------------------------------------
// Kernel 1: QKV.  z=0 -> Q, z=1 -> K, z=2 -> V^T (smem-staged transpose)
// ---------------------------------------------------------------------------
__global__ __launch_bounds__(128, 2) void qkv_mma() {
    extern __shared__ char smraw[];
    const uint32_t smem = (uint32_t)__cvta_generic_to_shared(smraw);
    const int z = blockIdx.z;
    const int m0 = blockIdx.y * 128;
    const int n0 = blockIdx.x * 128;

    float acc[4][8][4];
    ZERO_ACC(acc);

    mma_mainloop(g_x + (size_t)m0 * DD, g_w[z] + (size_t)n0 * DD,
                 DD, DD, DD / 64, smem, acc);

    const int lane = threadIdx.x & 31, wid = threadIdx.x >> 5;
    const int wm = wid >> 1, wn = wid & 1;
    const int g = lane >> 2, tg = lane & 3;

    if (z < 2) {
        __half* D = z ? g_k : g_q;
#pragma unroll
        for (int fm = 0; fm < 4; fm++)
#pragma unroll
            for (int fn = 0; fn < 8; fn++) {
                const int n = n0 + wn * 64 + fn * 8 + tg * 2;
#pragma unroll
                for (int half = 0; half < 2; half++) {
                    const int m = m0 + wm * 64 + fm * 16 + g + half * 8;
                    __half2 h2;
                    h2.x = __float2half(acc[fm][fn][half * 2]);
                    h2.y = __float2half(acc[fm][fn][half * 2 + 1]);
                    *(__half2*)(D + (size_t)m * DD + n) = h2;
                }
            }
    } else {
        // transpose 128x128 tile through smem, then coalesced store to V^T
        __syncthreads();                      // mainloop smem reads done
        __half* smt = (__half*)smraw;         // [n_local][m_local], stride 136
#pragma unroll
        for (int fm = 0; fm < 4; fm++)
#pragma unroll
            for (int fn = 0; fn < 8; fn++) {
                const int nl = wn * 64 + fn * 8 + tg * 2;
#pragma unroll
                for (int half = 0; half < 2; half++) {
                    const int ml = wm * 64 + fm * 16 + g + half * 8;
                    smt[(nl)     * 136 + ml] = __float2half(acc[fm][fn][half * 2]);
                    smt[(nl + 1) * 136 + ml] = __float2half(acc[fm][fn][half * 2 + 1]);
                }
            }
        __syncthreads();
        const int b = m0 >> 11, ml0 = m0 & (SS - 1);
        const size_t rowbase = (size_t)b * DD * SS + (size_t)(n0 + threadIdx.x) * SS + ml0;
#pragma unroll
        for (int c16 = 0; c16 < 16; c16++) {
            uint4 v = *(uint4*)(smt + threadIdx.x * 136 + c16 * 8);
            *(uint4*)(g_vT + rowbase + c16 * 8) = v;
        }
    }
}

// ---------------------------------------------------------------------------
// Kernel 2: causal scores -> p~ = exp(s/32) fp16 (masked) + fused row sums
// Lower-triangular 128x128 tiles only (136 per batch).
// ---------------------------------------------------------------------------
__global__ __launch_bounds__(128, 2) void scores_mma() {
    extern __shared__ char smraw[];
    const uint32_t smem = (uint32_t)__cvta_generic_to_shared(smraw);
    const int t = blockIdx.x;
    int it = (int)floorf((sqrtf(8.0f * (float)t + 1.0f) - 1.0f) * 0.5f);
    while ((it + 1) * (it + 2) / 2 <= t) ++it;
    while (it * (it + 1) / 2 > t) --it;
    const int jt = t - it * (it + 1) / 2;
    const int b = blockIdx.y;
    const int m0 = it * 128, n0 = jt * 128;

    float acc[4][8][4];
    ZERO_ACC(acc);

    const size_t ao = ((size_t)b * SS + m0) * DD;
    const size_t bo = ((size_t)b * SS + n0) * DD;
    mma_mainloop(g_q + ao, g_k + bo, DD, DD, DD / 64, smem, acc);

    const int lane = threadIdx.x & 31, wid = threadIdx.x >> 5;
    const int wm = wid >> 1, wn = wid & 1;
    const int g = lane >> 2, tg = lane & 3;
    __half* C = g_ph + (size_t)b * SS * SS;
    const float alpha = 1.0f / 32.0f;
    const bool diag = (it == jt);

#pragma unroll
    for (int fm = 0; fm < 4; fm++) {
#pragma unroll
        for (int half = 0; half < 2; half++) {
            const int m = m0 + wm * 64 + fm * 16 + g + half * 8;
            float rsum = 0.0f;
#pragma unroll
            for (int fn = 0; fn < 8; fn++) {
                const int n = n0 + wn * 64 + fn * 8 + tg * 2;
                float e0 = __expf(acc[fm][fn][half * 2] * alpha);
                float e1 = __expf(acc[fm][fn][half * 2 + 1] * alpha);
                if (diag) {
                    if (n > m) e0 = 0.0f;
                    if (n + 1 > m) e1 = 0.0f;
                }
                rsum += e0 + e1;
                __half2 h2; h2.x = __float2half(e0); h2.y = __float2half(e1);
                *(__half2*)(C + (size_t)m * SS + n) = h2;
            }
            // reduce across the 4 tg lanes (same row m)
            rsum += __shfl_xor_sync(0xffffffffu, rsum, 1);
            rsum += __shfl_xor_sync(0xffffffffu, rsum, 2);
            if (tg == 0) atomicAdd(&g_sum[b * SS + m], rsum);
        }
    }
}

// ---------------------------------------------------------------------------
// Kernel 3: O = (p~ @ V) / row_sum.  Longest row-tiles first.
// ---------------------------------------------------------------------------
__global__ __launch_bounds__(128, 2) void pv_mma(float* __restrict__ out) {
    extern __shared__ char smraw[];
    const uint32_t smem = (uint32_t)__cvta_generic_to_shared(smraw);
    const int b = blockIdx.z;
    const int it = (SS / 128 - 1) - blockIdx.y;   // 15..0, big tiles first
    const int m0 = it * 128;
    const int n0 = blockIdx.x * 128;
    const int nch = (it + 1) * 2;                 // kend = (it+1)*128, chunks of 64

    float acc[4][8][4];
    ZERO_ACC(acc);

    const size_t ao = ((size_t)b * SS + m0) * SS;
    const size_t bo = (size_t)b * DD * SS + (size_t)n0 * SS;
    mma_mainloop(g_ph + ao, g_vT + bo, SS, SS, nch, smem, acc);

    const int lane = threadIdx.x & 31, wid = threadIdx.x >> 5;
    const int wm = wid >> 1, wn = wid & 1;
    const int g = lane >> 2, tg = lane & 3;
    float* C = out + (size_t)b * SS * DD;

    float invm[4][2];
#pragma unroll
    for (int fm = 0; fm < 4; fm++)
#pragma unroll
        for (int half = 0; half < 2; half++)
            invm[fm][half] = 1.0f / g_sum[b * SS + m0 + wm * 64 + fm * 16 + g + half * 8];

#pragma unroll
    for (int fm = 0; fm < 4; fm++)
#pragma unroll
        for (int fn = 0; fn < 8; fn++) {
            const int n = n0 + wn * 64 + fn * 8 + tg * 2;
#pragma unroll
            for (int half = 0; half < 2; half++) {
                const int m = m0 + wm * 64 + fm * 16 + g + half * 8;
                float2 v;
                v.x = acc[fm][fn][half * 2]     * invm[fm][half];
                v.y = acc[fm][fn][half * 2 + 1] * invm[fm][half];
                *(float2*)(C + (size_t)m * DD + n) = v;
            }
        }
}

// ---------------------------------------------------------------------------
extern "C" void kernel_launch(void* const* d_in, const int* in_sizes, int n_in,
                              void* d_out, int out_size) {
    const float* x  = (const float*)d_in[0];
    const float* wq = (const float*)d_in[1];
    const float* wk = (const float*)d_in[2];
    const float* wv = (const float*)d_in[3];
    float* out = (float*)d_out;
    (void)in_sizes; (void)n_in; (void)out_size;

    static bool attr_done = false;
    if (!attr_done) {
        cudaFuncSetAttribute(qkv_mma,    cudaFuncAttributeMaxDynamicSharedMemorySize, SMEM_BYTES);
        cudaFuncSetAttribute(scores_mma, cudaFuncAttributeMaxDynamicSharedMemorySize, SMEM_BYTES);
        cudaFuncSetAttribute(pv_mma,     cudaFuncAttributeMaxDynamicSharedMemorySize, SMEM_BYTES);
        attr_done = true;
    }

    // 0) convert x, W to fp16; zero row sums
    convert_all<<<dim3(1024, 4), 256>>>(x, wq, wk, wv);

    // 1) Q, K, V^T projections
    qkv_mma<<<dim3(DD / 128, (BB * SS) / 128, 3), 128, SMEM_BYTES>>>();

    // 2) causal scores -> exp(s/32) fp16 (masked) + fused row sums
    const int ntri = (SS / 128) * (SS / 128 + 1) / 2;   // 136
    scores_mma<<<dim3(ntri, BB), 128, SMEM_BYTES>>>();

    // 3) O = (p~ @ V) / sum
    pv_mma<<<dim3(DD / 128, SS / 128, BB), 128, SMEM_BYTES>>>(out);
}